// round 2
// baseline (speedup 1.0000x reference)
#include <cuda_runtime.h>
#include <math.h>

// ---------------- problem constants ----------------
#define Bs      8
#define HEAD    512
#define FMP     40
#define NPOS    1600      // FMP*FMP
#define NCLS    20
#define CONF_T  0.001f
#define NMS_T   0.6f

// output layout (float32): bboxes | best | cls_inds | keep
#define OFF_BEST  (Bs*NPOS*4)          // 51200
#define OFF_CLS   (OFF_BEST + Bs*NPOS) // 64000
#define OFF_KEEP  (OFF_CLS  + Bs*NPOS) // 76800

// ---------------- scratch (device globals, no runtime alloc) ----------------
__device__ float g_bufA[Bs * HEAD * NPOS];
__device__ float g_bufB[Bs * HEAD * NPOS];
__device__ float g_bufC[Bs * HEAD * NPOS];
__device__ float g_best[Bs * NPOS];
__device__ int   g_clsi[Bs * NPOS];

// ---------------- conv 3x3 (pad 1) + bias + leaky ----------------
// grid: (40 y-rows, 4 oc-groups of 128, 8 batch), block: 128 threads
// thread: og = tid>>2 (0..31) -> 4 output channels og*4+j ; xs = tid&3 -> x in [xs*10, xs*10+10)
__global__ void __launch_bounds__(128)
conv3x3_leaky_k(const float* __restrict__ in, const float* __restrict__ w,
                const float* __restrict__ bias, float* __restrict__ out)
{
    const int y   = blockIdx.x;
    const int ocg = blockIdx.y;
    const int b   = blockIdx.z;
    const int tid = threadIdx.x;
    const int og  = tid >> 2;
    const int xs  = tid & 3;
    const int x0  = xs * 10;

    __shared__ float s_in[8 * 3 * 42];   // [ic][ky][xx], xx = x+1 (pad)
    __shared__ float s_w[128 * 73];      // [oc][kk] padded stride 73 (kk = ic*9 + ky*3 + kx)

    float acc[4][10];
#pragma unroll
    for (int j = 0; j < 4; j++)
#pragma unroll
        for (int xx = 0; xx < 10; xx++) acc[j][xx] = 0.f;

    const float* inb = in + (long)b * HEAD * NPOS;
    const float* wb  = w + (long)(ocg * 128) * (HEAD * 9);

    for (int ic0 = 0; ic0 < HEAD; ic0 += 8) {
        __syncthreads();
        // stage input tile: 8 ic x 3 rows x 42 (zero-padded)
        for (int idx = tid; idx < 8 * 3 * 42; idx += 128) {
            int ic = idx / 126;
            int r2 = idx - ic * 126;
            int ky = r2 / 42;
            int xx = r2 - ky * 42;
            int yy = y + ky - 1;
            int xg = xx - 1;
            float v = 0.f;
            if ((unsigned)yy < (unsigned)FMP && (unsigned)xg < (unsigned)FMP)
                v = inb[(ic0 + ic) * NPOS + yy * FMP + xg];
            s_in[idx] = v;
        }
        // stage weights: 128 oc x 72 contiguous floats each (coalesced, conflict-free store)
        for (int idx = tid; idx < 128 * 72; idx += 128) {
            int oc = idx / 72;
            int kk = idx - oc * 72;
            s_w[oc * 73 + kk] = wb[oc * (HEAD * 9) + ic0 * 9 + kk];
        }
        __syncthreads();

#pragma unroll 2
        for (int ic = 0; ic < 8; ic++) {
#pragma unroll
            for (int ky = 0; ky < 3; ky++) {
                float r[12];
                const float* sr = &s_in[(ic * 3 + ky) * 42 + x0];
#pragma unroll
                for (int i = 0; i < 12; i++) r[i] = sr[i];
#pragma unroll
                for (int kx = 0; kx < 3; kx++) {
                    float wv[4];
#pragma unroll
                    for (int j = 0; j < 4; j++)
                        wv[j] = s_w[(og * 4 + j) * 73 + ic * 9 + ky * 3 + kx];
#pragma unroll
                    for (int xx = 0; xx < 10; xx++) {
                        float iv = r[xx + kx];
#pragma unroll
                        for (int j = 0; j < 4; j++)
                            acc[j][xx] = fmaf(wv[j], iv, acc[j][xx]);
                    }
                }
            }
        }
    }

#pragma unroll
    for (int j = 0; j < 4; j++) {
        int oc = ocg * 128 + og * 4 + j;
        float bv = bias[oc];
        float* ob = out + ((long)b * HEAD + oc) * NPOS + y * FMP + x0;
#pragma unroll
        for (int xx = 0; xx < 10; xx++) {
            float v = acc[j][xx] + bv;
            ob[xx] = v > 0.f ? v : 0.1f * v;
        }
    }
}

// ---------------- 1x1 heads + decode (boxes, best, argmax, keep init) ----------------
// grid: (10, 8), block 160 -> one thread per spatial position
__global__ void __launch_bounds__(160)
heads_decode_k(const float* __restrict__ cf, const float* __restrict__ rf,
               const float* __restrict__ obj_w, const float* __restrict__ obj_b,
               const float* __restrict__ clsp_w, const float* __restrict__ clsp_b,
               const float* __restrict__ regp_w, const float* __restrict__ regp_b,
               float* __restrict__ out, float* __restrict__ best_s, int* __restrict__ cls_s)
{
    const int b = blockIdx.y;
    const int n = blockIdx.x * 160 + threadIdx.x;

    const float* cfb = cf + (long)b * HEAD * NPOS + n;
    const float* rfb = rf + (long)b * HEAD * NPOS + n;

    float accC[NCLS];
    float accR[4];
    float accO = 0.f;
#pragma unroll
    for (int c = 0; c < NCLS; c++) accC[c] = 0.f;
#pragma unroll
    for (int k = 0; k < 4; k++) accR[k] = 0.f;

#pragma unroll 4
    for (int ch = 0; ch < HEAD; ch++) {
        float cv = cfb[(long)ch * NPOS];
        float rv = rfb[(long)ch * NPOS];
        accO = fmaf(rv, __ldg(&obj_w[ch]), accO);
#pragma unroll
        for (int k = 0; k < 4; k++)
            accR[k] = fmaf(rv, __ldg(&regp_w[k * HEAD + ch]), accR[k]);
#pragma unroll
        for (int c = 0; c < NCLS; c++)
            accC[c] = fmaf(cv, __ldg(&clsp_w[c * HEAD + ch]), accC[c]);
    }

    accO += obj_b[0];
#pragma unroll
    for (int k = 0; k < 4; k++) accR[k] += regp_b[k];
#pragma unroll
    for (int c = 0; c < NCLS; c++) accC[c] += clsp_b[c];

    // softmax max / argmax (first-max tie-break, matching jnp.argmax)
    float m = accC[0];
    int am = 0;
#pragma unroll
    for (int c = 1; c < NCLS; c++)
        if (accC[c] > m) { m = accC[c]; am = c; }
    float s = 0.f;
#pragma unroll
    for (int c = 0; c < NCLS; c++) s += expf(accC[c] - m);
    float sig_o = 1.f / (1.f + expf(-accO));
    float best  = sig_o / s;   // sigmoid(obj) * softmax_max

    // box decode
    float gx = (float)(n % FMP);
    float gy = (float)(n / FMP);
    float cx = 1.f / (1.f + expf(-accR[0])) + gx;
    float cy = 1.f / (1.f + expf(-accR[1])) + gy;
    float ww = expf(accR[2]);
    float hh = expf(accR[3]);

    float bx1 = (cx - ww * 0.5f) * 32.f / 1280.f;
    float by1 = (cy - hh * 0.5f) * 32.f / 1280.f;
    float bx2 = (cx + ww * 0.5f) * 32.f / 1280.f;
    float by2 = (cy + hh * 0.5f) * 32.f / 1280.f;
    bx1 = fminf(fmaxf(bx1, 0.f), 1.f);
    by1 = fminf(fmaxf(by1, 0.f), 1.f);
    bx2 = fminf(fmaxf(bx2, 0.f), 1.f);
    by2 = fminf(fmaxf(by2, 0.f), 1.f);

    const int gi = b * NPOS + n;
    out[gi * 4 + 0] = bx1;
    out[gi * 4 + 1] = by1;
    out[gi * 4 + 2] = bx2;
    out[gi * 4 + 3] = by2;
    out[OFF_BEST + gi] = best;
    out[OFF_CLS  + gi] = (float)am;
    out[OFF_KEEP + gi] = 0.f;     // NMS sets kept ones to 1
    best_s[gi] = best;
    cls_s[gi]  = am;
}

// ---------------- per-(batch, class) greedy NMS ----------------
// grid: B*C = 160 blocks, 256 threads
__global__ void __launch_bounds__(256)
nms_k(const float* __restrict__ out_boxes,  // d_out (bbox region at offset 0)
      float* __restrict__ out_keep,         // d_out + OFF_KEEP
      const float* __restrict__ best_s, const int* __restrict__ cls_s)
{
    const int b = blockIdx.x / NCLS;
    const int c = blockIdx.x % NCLS;
    const int tid = threadIdx.x;

    __shared__ float sx1[NPOS], sy1[NPOS], sx2[NPOS], sy2[NPOS];
    __shared__ float ssc[NPOS];
    __shared__ int   sidx[NPOS];
    __shared__ unsigned short ord[NPOS];
    __shared__ unsigned char aliveR[NPOS];
    __shared__ int scnt;

    if (tid == 0) scnt = 0;
    __syncthreads();

    // gather candidates of this class
    for (int n = tid; n < NPOS; n += 256) {
        int gi = b * NPOS + n;
        if (cls_s[gi] == c && best_s[gi] >= CONF_T) {
            int p = atomicAdd(&scnt, 1);
            sidx[p] = n;
            ssc[p]  = best_s[gi];
            const float* bp = out_boxes + (long)gi * 4;
            sx1[p] = bp[0]; sy1[p] = bp[1]; sx2[p] = bp[2]; sy2[p] = bp[3];
        }
    }
    __syncthreads();
    const int cnt = scnt;

    // deterministic rank: score desc, original index asc (matches stable argsort of -score)
    for (int i = tid; i < cnt; i += 256) {
        float si = ssc[i];
        int   ii = sidx[i];
        int rnk = 0;
        for (int j = 0; j < cnt; j++) {
            float sj = ssc[j];
            if (sj > si || (sj == si && sidx[j] < ii)) rnk++;
        }
        ord[rnk] = (unsigned short)i;
        aliveR[rnk] = 1;
    }
    __syncthreads();

    // sequential greedy over rank order; parallel suppression within block
    for (int r = 0; r < cnt; r++) {
        __syncthreads();
        if (!aliveR[r]) continue;        // uniform (shared, post-sync)
        int li = ord[r];
        float bx1 = sx1[li], by1 = sy1[li], bx2 = sx2[li], by2 = sy2[li];
        float ai = (bx2 - bx1) * (by2 - by1);
        for (int rr = r + 1 + tid; rr < cnt; rr += 256) {
            if (!aliveR[rr]) continue;
            int lj = ord[rr];
            float jx1 = sx1[lj], jy1 = sy1[lj], jx2 = sx2[lj], jy2 = sy2[lj];
            float xx1 = fmaxf(bx1, jx1);
            float yy1 = fmaxf(by1, jy1);
            float xx2 = fminf(bx2, jx2);
            float yy2 = fminf(by2, jy2);
            float w2 = fmaxf(1e-28f, xx2 - xx1);
            float h2 = fmaxf(1e-28f, yy2 - yy1);
            float inter = w2 * h2;
            float aj = (jx2 - jx1) * (jy2 - jy1);
            float iou = inter / (ai + aj - inter + 1e-14f);
            if (iou > NMS_T) aliveR[rr] = 0;
        }
    }
    __syncthreads();

    for (int r = tid; r < cnt; r += 256)
        if (aliveR[r])
            out_keep[b * NPOS + sidx[ord[r]]] = 1.f;
}

// ---------------- launch ----------------
extern "C" void kernel_launch(void* const* d_in, const int* in_sizes, int n_in,
                              void* d_out, int out_size)
{
    const float* x      = (const float*)d_in[0];
    const float* cls_w  = (const float*)d_in[1];
    const float* cls_b  = (const float*)d_in[2];
    const float* reg_w  = (const float*)d_in[3];
    const float* reg_b  = (const float*)d_in[4];
    const float* obj_w  = (const float*)d_in[5];
    const float* obj_b  = (const float*)d_in[6];
    const float* clsp_w = (const float*)d_in[7];
    const float* clsp_b = (const float*)d_in[8];
    const float* regp_w = (const float*)d_in[9];
    const float* regp_b = (const float*)d_in[10];
    float* out = (float*)d_out;

    void *pA, *pB, *pC, *pBest, *pCls;
    cudaGetSymbolAddress(&pA, g_bufA);
    cudaGetSymbolAddress(&pB, g_bufB);
    cudaGetSymbolAddress(&pC, g_bufC);
    cudaGetSymbolAddress(&pBest, g_best);
    cudaGetSymbolAddress(&pCls, g_clsi);
    float* bufA = (float*)pA;
    float* bufB = (float*)pB;
    float* bufC = (float*)pC;
    float* bestp = (float*)pBest;
    int*   clsp  = (int*)pCls;

    dim3 cgrid(FMP, 4, Bs);
    dim3 cblk(128);
    const long WSTRIDE = (long)HEAD * HEAD * 9;

    // cls branch: x -> bufA -> bufB   (cf = bufB)
    conv3x3_leaky_k<<<cgrid, cblk>>>(x,    cls_w,             cls_b,        bufA);
    conv3x3_leaky_k<<<cgrid, cblk>>>(bufA, cls_w + WSTRIDE,   cls_b + HEAD, bufB);
    // reg branch: x -> bufA -> bufC -> bufA -> bufC   (rf = bufC)
    conv3x3_leaky_k<<<cgrid, cblk>>>(x,    reg_w,               reg_b,            bufA);
    conv3x3_leaky_k<<<cgrid, cblk>>>(bufA, reg_w + WSTRIDE,     reg_b + HEAD,     bufC);
    conv3x3_leaky_k<<<cgrid, cblk>>>(bufC, reg_w + 2 * WSTRIDE, reg_b + 2 * HEAD, bufA);
    conv3x3_leaky_k<<<cgrid, cblk>>>(bufA, reg_w + 3 * WSTRIDE, reg_b + 3 * HEAD, bufC);

    heads_decode_k<<<dim3(10, Bs), 160>>>(bufB, bufC,
                                          obj_w, obj_b, clsp_w, clsp_b,
                                          regp_w, regp_b,
                                          out, bestp, clsp);

    nms_k<<<Bs * NCLS, 256>>>(out, out + OFF_KEEP, bestp, clsp);
}

// round 3
// speedup vs baseline: 1.0430x; 1.0430x over previous
#include <cuda_runtime.h>
#include <math.h>

// ---------------- problem constants ----------------
#define Bs      8
#define HEAD    512
#define FMP     40
#define NPOS    1600      // FMP*FMP
#define NCLS    20
#define CONF_T  0.001f
#define NMS_T   0.6f

// output layout (float32): bboxes | best | cls_inds | keep
#define OFF_BEST  (Bs*NPOS*4)          // 51200
#define OFF_CLS   (OFF_BEST + Bs*NPOS) // 64000
#define OFF_KEEP  (OFF_CLS  + Bs*NPOS) // 76800

// ---------------- scratch (device globals, no runtime alloc) ----------------
__device__ float g_bufA[Bs * HEAD * NPOS];
__device__ float g_bufB[Bs * HEAD * NPOS];
__device__ float g_bufC[Bs * HEAD * NPOS];
__device__ float g_best[Bs * NPOS];
__device__ int   g_clsi[Bs * NPOS];

// ---------------- packed f32x2 helpers ----------------
__device__ __forceinline__ void fma2(float2 &d, float2 a, float2 b) {
    asm("fma.rn.f32x2 %0, %1, %2, %0;"
        : "+l"(reinterpret_cast<unsigned long long&>(d))
        : "l"(reinterpret_cast<unsigned long long&>(a)),
          "l"(reinterpret_cast<unsigned long long&>(b)));
}
__device__ __forceinline__ float2 dupw(float w) {
    float2 r;
    asm("mov.b64 %0, {%1, %1};"
        : "=l"(reinterpret_cast<unsigned long long&>(r)) : "f"(w));
    return r;
}

// ---------------- conv 3x3 (pad 1) + bias + leaky, f32x2 packed ----------------
// grid: (40 y-rows, 4 oc-groups of 128, 8 batch), block: 128 threads
// thread: og = tid>>2 (0..31) -> 4 output channels og*4+j ; xs = tid&3 -> x in [xs*10, xs*10+10)
// accumulators packed over x-pairs: acc2[j][p] covers x = x0+2p, x0+2p+1
__global__ void __launch_bounds__(128)
conv3x3_leaky_k(const float* __restrict__ in, const float* __restrict__ w,
                const float* __restrict__ bias, float* __restrict__ out)
{
    const int y   = blockIdx.x;
    const int ocg = blockIdx.y;
    const int b   = blockIdx.z;
    const int tid = threadIdx.x;
    const int og  = tid >> 2;
    const int xs  = tid & 3;
    const int x0  = xs * 10;

    __shared__ float s_in[8 * 3 * 42];   // [ic][ky][xx], xx = x+1 (pad)
    __shared__ float s_w[128 * 73];      // [oc][kk] padded stride 73 (kk = ic*9 + ky*3 + kx)

    float2 acc2[4][5];
#pragma unroll
    for (int j = 0; j < 4; j++)
#pragma unroll
        for (int p = 0; p < 5; p++) acc2[j][p] = make_float2(0.f, 0.f);

    const float* inb = in + (long)b * HEAD * NPOS;
    const float* wb  = w + (long)(ocg * 128) * (HEAD * 9);
    const int wrow = (og * 4) * 73;      // this thread's first oc row in s_w

    for (int ic0 = 0; ic0 < HEAD; ic0 += 8) {
        __syncthreads();
        // stage input tile: 8 ic x 3 rows x 42 (zero-padded)
        for (int idx = tid; idx < 8 * 3 * 42; idx += 128) {
            int ic = idx / 126;
            int r2 = idx - ic * 126;
            int ky = r2 / 42;
            int xx = r2 - ky * 42;
            int yy = y + ky - 1;
            int xg = xx - 1;
            float v = 0.f;
            if ((unsigned)yy < (unsigned)FMP && (unsigned)xg < (unsigned)FMP)
                v = inb[(ic0 + ic) * NPOS + yy * FMP + xg];
            s_in[idx] = v;
        }
        // stage weights: 128 oc x 72 contiguous floats each
        for (int idx = tid; idx < 128 * 72; idx += 128) {
            int oc = idx / 72;
            int kk = idx - oc * 72;
            s_w[oc * 73 + kk] = wb[oc * (HEAD * 9) + ic0 * 9 + kk];
        }
        __syncthreads();

#pragma unroll 2
        for (int ic = 0; ic < 8; ic++) {
            const int kkb = ic * 9;
#pragma unroll
            for (int ky = 0; ky < 3; ky++) {
                const float* sr = &s_in[(ic * 3 + ky) * 42 + x0];   // 8B-aligned (x0 even, row stride 42 even)
                float2 e[6];
#pragma unroll
                for (int i = 0; i < 6; i++)
                    e[i] = *reinterpret_cast<const float2*>(sr + 2 * i);   // (r[2i], r[2i+1])
                float2 o[5];
#pragma unroll
                for (int p = 0; p < 5; p++)
                    o[p] = make_float2(e[p].y, e[p + 1].x);                // (r[2p+1], r[2p+2])

#pragma unroll
                for (int kx = 0; kx < 3; kx++) {
#pragma unroll
                    for (int j = 0; j < 4; j++) {
                        float2 wd = dupw(s_w[wrow + j * 73 + kkb + ky * 3 + kx]);
#pragma unroll
                        for (int p = 0; p < 5; p++) {
                            float2 iv = (kx == 0) ? e[p] : (kx == 1) ? o[p] : e[p + 1];
                            fma2(acc2[j][p], wd, iv);
                        }
                    }
                }
            }
        }
    }

#pragma unroll
    for (int j = 0; j < 4; j++) {
        int oc = ocg * 128 + og * 4 + j;
        float bv = bias[oc];
        float* ob = out + ((long)b * HEAD + oc) * NPOS + y * FMP + x0;  // 8B-aligned (x0 even, NPOS even)
#pragma unroll
        for (int p = 0; p < 5; p++) {
            float v0 = acc2[j][p].x + bv;
            float v1 = acc2[j][p].y + bv;
            float2 r;
            r.x = v0 > 0.f ? v0 : 0.1f * v0;
            r.y = v1 > 0.f ? v1 : 0.1f * v1;
            *reinterpret_cast<float2*>(ob + 2 * p) = r;
        }
    }
}

// ---------------- 1x1 heads + decode (boxes, best, argmax, keep init) ----------------
// grid: (10, 8), block 160 -> one thread per spatial position
__global__ void __launch_bounds__(160)
heads_decode_k(const float* __restrict__ cf, const float* __restrict__ rf,
               const float* __restrict__ obj_w, const float* __restrict__ obj_b,
               const float* __restrict__ clsp_w, const float* __restrict__ clsp_b,
               const float* __restrict__ regp_w, const float* __restrict__ regp_b,
               float* __restrict__ out, float* __restrict__ best_s, int* __restrict__ cls_s)
{
    const int b = blockIdx.y;
    const int n = blockIdx.x * 160 + threadIdx.x;

    const float* cfb = cf + (long)b * HEAD * NPOS + n;
    const float* rfb = rf + (long)b * HEAD * NPOS + n;

    float accC[NCLS];
    float accR[4];
    float accO = 0.f;
#pragma unroll
    for (int c = 0; c < NCLS; c++) accC[c] = 0.f;
#pragma unroll
    for (int k = 0; k < 4; k++) accR[k] = 0.f;

#pragma unroll 4
    for (int ch = 0; ch < HEAD; ch++) {
        float cv = cfb[(long)ch * NPOS];
        float rv = rfb[(long)ch * NPOS];
        accO = fmaf(rv, __ldg(&obj_w[ch]), accO);
#pragma unroll
        for (int k = 0; k < 4; k++)
            accR[k] = fmaf(rv, __ldg(&regp_w[k * HEAD + ch]), accR[k]);
#pragma unroll
        for (int c = 0; c < NCLS; c++)
            accC[c] = fmaf(cv, __ldg(&clsp_w[c * HEAD + ch]), accC[c]);
    }

    accO += obj_b[0];
#pragma unroll
    for (int k = 0; k < 4; k++) accR[k] += regp_b[k];
#pragma unroll
    for (int c = 0; c < NCLS; c++) accC[c] += clsp_b[c];

    // softmax max / argmax (first-max tie-break, matching jnp.argmax)
    float m = accC[0];
    int am = 0;
#pragma unroll
    for (int c = 1; c < NCLS; c++)
        if (accC[c] > m) { m = accC[c]; am = c; }
    float s = 0.f;
#pragma unroll
    for (int c = 0; c < NCLS; c++) s += expf(accC[c] - m);
    float sig_o = 1.f / (1.f + expf(-accO));
    float best  = sig_o / s;   // sigmoid(obj) * softmax_max

    // box decode
    float gx = (float)(n % FMP);
    float gy = (float)(n / FMP);
    float cx = 1.f / (1.f + expf(-accR[0])) + gx;
    float cy = 1.f / (1.f + expf(-accR[1])) + gy;
    float ww = expf(accR[2]);
    float hh = expf(accR[3]);

    float bx1 = (cx - ww * 0.5f) * 32.f / 1280.f;
    float by1 = (cy - hh * 0.5f) * 32.f / 1280.f;
    float bx2 = (cx + ww * 0.5f) * 32.f / 1280.f;
    float by2 = (cy + hh * 0.5f) * 32.f / 1280.f;
    bx1 = fminf(fmaxf(bx1, 0.f), 1.f);
    by1 = fminf(fmaxf(by1, 0.f), 1.f);
    bx2 = fminf(fmaxf(bx2, 0.f), 1.f);
    by2 = fminf(fmaxf(by2, 0.f), 1.f);

    const int gi = b * NPOS + n;
    out[gi * 4 + 0] = bx1;
    out[gi * 4 + 1] = by1;
    out[gi * 4 + 2] = bx2;
    out[gi * 4 + 3] = by2;
    out[OFF_BEST + gi] = best;
    out[OFF_CLS  + gi] = (float)am;
    out[OFF_KEEP + gi] = 0.f;     // NMS sets kept ones to 1
    best_s[gi] = best;
    cls_s[gi]  = am;
}

// ---------------- per-(batch, class) greedy NMS ----------------
// grid: B*C = 160 blocks, 256 threads
__global__ void __launch_bounds__(256)
nms_k(const float* __restrict__ out_boxes,  // d_out (bbox region at offset 0)
      float* __restrict__ out_keep,         // d_out + OFF_KEEP
      const float* __restrict__ best_s, const int* __restrict__ cls_s)
{
    const int b = blockIdx.x / NCLS;
    const int c = blockIdx.x % NCLS;
    const int tid = threadIdx.x;

    __shared__ float sx1[NPOS], sy1[NPOS], sx2[NPOS], sy2[NPOS];
    __shared__ float ssc[NPOS];
    __shared__ int   sidx[NPOS];
    __shared__ unsigned short ord[NPOS];
    __shared__ unsigned char aliveR[NPOS];
    __shared__ int scnt;

    if (tid == 0) scnt = 0;
    __syncthreads();

    // gather candidates of this class
    for (int n = tid; n < NPOS; n += 256) {
        int gi = b * NPOS + n;
        if (cls_s[gi] == c && best_s[gi] >= CONF_T) {
            int p = atomicAdd(&scnt, 1);
            sidx[p] = n;
            ssc[p]  = best_s[gi];
            const float* bp = out_boxes + (long)gi * 4;
            sx1[p] = bp[0]; sy1[p] = bp[1]; sx2[p] = bp[2]; sy2[p] = bp[3];
        }
    }
    __syncthreads();
    const int cnt = scnt;

    // deterministic rank: score desc, original index asc (matches stable argsort of -score)
    for (int i = tid; i < cnt; i += 256) {
        float si = ssc[i];
        int   ii = sidx[i];
        int rnk = 0;
        for (int j = 0; j < cnt; j++) {
            float sj = ssc[j];
            if (sj > si || (sj == si && sidx[j] < ii)) rnk++;
        }
        ord[rnk] = (unsigned short)i;
        aliveR[rnk] = 1;
    }
    __syncthreads();

    // sequential greedy over rank order; parallel suppression within block
    for (int r = 0; r < cnt; r++) {
        __syncthreads();
        if (!aliveR[r]) continue;        // uniform (shared, post-sync)
        int li = ord[r];
        float bx1 = sx1[li], by1 = sy1[li], bx2 = sx2[li], by2 = sy2[li];
        float ai = (bx2 - bx1) * (by2 - by1);
        for (int rr = r + 1 + tid; rr < cnt; rr += 256) {
            if (!aliveR[rr]) continue;
            int lj = ord[rr];
            float jx1 = sx1[lj], jy1 = sy1[lj], jx2 = sx2[lj], jy2 = sy2[lj];
            float xx1 = fmaxf(bx1, jx1);
            float yy1 = fmaxf(by1, jy1);
            float xx2 = fminf(bx2, jx2);
            float yy2 = fminf(by2, jy2);
            float w2 = fmaxf(1e-28f, xx2 - xx1);
            float h2 = fmaxf(1e-28f, yy2 - yy1);
            float inter = w2 * h2;
            float aj = (jx2 - jx1) * (jy2 - jy1);
            float iou = inter / (ai + aj - inter + 1e-14f);
            if (iou > NMS_T) aliveR[rr] = 0;
        }
    }
    __syncthreads();

    for (int r = tid; r < cnt; r += 256)
        if (aliveR[r])
            out_keep[b * NPOS + sidx[ord[r]]] = 1.f;
}

// ---------------- launch ----------------
extern "C" void kernel_launch(void* const* d_in, const int* in_sizes, int n_in,
                              void* d_out, int out_size)
{
    const float* x      = (const float*)d_in[0];
    const float* cls_w  = (const float*)d_in[1];
    const float* cls_b  = (const float*)d_in[2];
    const float* reg_w  = (const float*)d_in[3];
    const float* reg_b  = (const float*)d_in[4];
    const float* obj_w  = (const float*)d_in[5];
    const float* obj_b  = (const float*)d_in[6];
    const float* clsp_w = (const float*)d_in[7];
    const float* clsp_b = (const float*)d_in[8];
    const float* regp_w = (const float*)d_in[9];
    const float* regp_b = (const float*)d_in[10];
    float* out = (float*)d_out;

    void *pA, *pB, *pC, *pBest, *pCls;
    cudaGetSymbolAddress(&pA, g_bufA);
    cudaGetSymbolAddress(&pB, g_bufB);
    cudaGetSymbolAddress(&pC, g_bufC);
    cudaGetSymbolAddress(&pBest, g_best);
    cudaGetSymbolAddress(&pCls, g_clsi);
    float* bufA = (float*)pA;
    float* bufB = (float*)pB;
    float* bufC = (float*)pC;
    float* bestp = (float*)pBest;
    int*   clsp  = (int*)pCls;

    dim3 cgrid(FMP, 4, Bs);
    dim3 cblk(128);
    const long WSTRIDE = (long)HEAD * HEAD * 9;

    // cls branch: x -> bufA -> bufB   (cf = bufB)
    conv3x3_leaky_k<<<cgrid, cblk>>>(x,    cls_w,             cls_b,        bufA);
    conv3x3_leaky_k<<<cgrid, cblk>>>(bufA, cls_w + WSTRIDE,   cls_b + HEAD, bufB);
    // reg branch: x -> bufA -> bufC -> bufA -> bufC   (rf = bufC)
    conv3x3_leaky_k<<<cgrid, cblk>>>(x,    reg_w,               reg_b,            bufA);
    conv3x3_leaky_k<<<cgrid, cblk>>>(bufA, reg_w + WSTRIDE,     reg_b + HEAD,     bufC);
    conv3x3_leaky_k<<<cgrid, cblk>>>(bufC, reg_w + 2 * WSTRIDE, reg_b + 2 * HEAD, bufA);
    conv3x3_leaky_k<<<cgrid, cblk>>>(bufA, reg_w + 3 * WSTRIDE, reg_b + 3 * HEAD, bufC);

    heads_decode_k<<<dim3(10, Bs), 160>>>(bufB, bufC,
                                          obj_w, obj_b, clsp_w, clsp_b,
                                          regp_w, regp_b,
                                          out, bestp, clsp);

    nms_k<<<Bs * NCLS, 256>>>(out, out + OFF_KEEP, bestp, clsp);
}

// round 4
// speedup vs baseline: 1.4189x; 1.3603x over previous
#include <cuda_runtime.h>
#include <math.h>

// ---------------- problem constants ----------------
#define Bs      8
#define HEAD    512
#define FMP     40
#define NPOS    1600      // FMP*FMP
#define NCLS    20
#define CONF_T  0.001f
#define NMS_T   0.6f

// output layout (float32): bboxes | best | cls_inds | keep
#define OFF_BEST  (Bs*NPOS*4)          // 51200
#define OFF_CLS   (OFF_BEST + Bs*NPOS) // 64000
#define OFF_KEEP  (OFF_CLS  + Bs*NPOS) // 76800

#define WPER (512L*4608L)              // floats per conv layer (512 oc x 512 ic x 9)

// ---------------- scratch (device globals, no runtime alloc) ----------------
__device__ float g_bufA[Bs * HEAD * NPOS];
__device__ float g_bufB[Bs * HEAD * NPOS];
__device__ float g_bufC[Bs * HEAD * NPOS];
__device__ float g_best[Bs * NPOS];
__device__ int   g_clsi[Bs * NPOS];
__device__ float g_wT[6 * WPER];       // transposed weights, 56.6 MB

// ---------------- packed f32x2 helper ----------------
__device__ __forceinline__ void fma2(float2 &d, float2 a, float2 b) {
    asm("fma.rn.f32x2 %0, %1, %2, %0;"
        : "+l"(reinterpret_cast<unsigned long long&>(d))
        : "l"(reinterpret_cast<unsigned long long&>(a)),
          "l"(reinterpret_cast<unsigned long long&>(b)));
}

// ---------------- weight pre-transform ----------------
// dst layout per layer: [ocg(4)][s(64)][kk(72)][oc_in(128)]
// src layout: [oc(512)][ic(512)][3][3]  ->  src[oc*4608 + s*72 + kk]
__global__ void __launch_bounds__(256)
wtransform_k(const float* __restrict__ cls_w, const float* __restrict__ reg_w,
             float* __restrict__ wT)
{
    long i = (long)blockIdx.x * 256 + threadIdx.x;
    if (i >= 6 * WPER) return;
    int  l  = (int)(i / WPER);
    long r  = i - (long)l * WPER;
    int  oc_in = (int)(r & 127);
    long t  = r >> 7;             // (ocg*64+s)*72 + kk
    int  kk = (int)(t % 72);
    long u  = t / 72;
    int  s  = (int)(u & 63);
    int  ocg = (int)(u >> 6);
    const float* src = (l < 2) ? (cls_w + (long)l * WPER)
                               : (reg_w + (long)(l - 2) * WPER);
    wT[i] = src[(long)(ocg * 128 + oc_in) * 4608 + s * 72 + kk];
}

// ---------------- conv 3x3 (pad 1) + bias + leaky, f32x2, oc-pair packed ----------------
// grid: (40 y-rows, 4 oc-groups of 128, 8 batch), block: 128 threads
// thread: og = tid>>2 (0..31) -> oc pairs (og*4, og*4+1), (og*4+2, og*4+3)
//         xs = tid&3 -> x in [xs*10, xs*10+10)
__global__ void __launch_bounds__(128)
conv3x3_leaky_k(const float* __restrict__ in, const float* __restrict__ wT,
                const float* __restrict__ bias, float* __restrict__ out)
{
    const int y   = blockIdx.x;
    const int ocg = blockIdx.y;
    const int b   = blockIdx.z;
    const int tid = threadIdx.x;
    const int og  = tid >> 2;
    const int xs  = tid & 3;
    const int x0  = xs * 10;

    __shared__ float2 s_in2[8 * 3 * 42];   // duplicated input pairs, 8064 B
    __shared__ float  s_w[72 * 128];       // [kk][oc_in], 36864 B

    float2 acc[2][10];
#pragma unroll
    for (int j = 0; j < 2; j++)
#pragma unroll
        for (int x = 0; x < 10; x++) acc[j][x] = make_float2(0.f, 0.f);

    const float* inb   = in + (long)b * HEAD * NPOS;
    const float* wbase = wT + (long)ocg * 64 * 72 * 128;

    for (int s = 0; s < 64; s++) {
        __syncthreads();
        // stage input tile: 8 ic x 3 rows x 42, duplicated into float2
        for (int idx = tid; idx < 8 * 3 * 42; idx += 128) {
            int ic = idx / 126;
            int r2 = idx - ic * 126;
            int ky = r2 / 42;
            int xx = r2 - ky * 42;
            int yy = y + ky - 1;
            int xg = xx - 1;
            float v = 0.f;
            if ((unsigned)yy < (unsigned)FMP && (unsigned)xg < (unsigned)FMP)
                v = inb[(s * 8 + ic) * NPOS + yy * FMP + xg];
            s_in2[idx] = make_float2(v, v);
        }
        // stage weights: contiguous 9216 floats = 2304 float4, coalesced
        {
            const float4* wsrc = (const float4*)(wbase + (long)s * 72 * 128);
            float4* wdst = (float4*)s_w;
#pragma unroll
            for (int k = 0; k < 18; k++)
                wdst[tid + 128 * k] = wsrc[tid + 128 * k];
        }
        __syncthreads();

#pragma unroll 2
        for (int ic = 0; ic < 8; ic++) {
#pragma unroll
            for (int ky = 0; ky < 3; ky++) {
                const float2* sr = s_in2 + (ic * 3 + ky) * 42 + x0;
                float2 iv[12];
#pragma unroll
                for (int i = 0; i < 12; i++) iv[i] = sr[i];

                const float2* wrow =
                    (const float2*)(s_w + (ic * 9 + ky * 3) * 128) + og * 2;
#pragma unroll
                for (int kx = 0; kx < 3; kx++) {
                    float2 w0 = wrow[kx * 64 + 0];   // oc pair (og*4, og*4+1)
                    float2 w1 = wrow[kx * 64 + 1];   // oc pair (og*4+2, og*4+3)
#pragma unroll
                    for (int x = 0; x < 10; x++) {
                        fma2(acc[0][x], w0, iv[x + kx]);
                        fma2(acc[1][x], w1, iv[x + kx]);
                    }
                }
            }
        }
    }

#pragma unroll
    for (int j2 = 0; j2 < 2; j2++) {
        int oc0 = ocg * 128 + og * 4 + j2 * 2;
        float b0 = bias[oc0];
        float b1 = bias[oc0 + 1];
        float* o0 = out + ((long)b * HEAD + oc0) * NPOS + y * FMP + x0;
        float* o1 = o0 + NPOS;
#pragma unroll
        for (int x = 0; x < 10; x++) {
            float v0 = acc[j2][x].x + b0;
            float v1 = acc[j2][x].y + b1;
            o0[x] = v0 > 0.f ? v0 : 0.1f * v0;
            o1[x] = v1 > 0.f ? v1 : 0.1f * v1;
        }
    }
}

// ---------------- 1x1 heads + decode (boxes, best, argmax, keep init) ----------------
// grid: (10, 8), block 160 -> one thread per spatial position
__global__ void __launch_bounds__(160)
heads_decode_k(const float* __restrict__ cf, const float* __restrict__ rf,
               const float* __restrict__ obj_w, const float* __restrict__ obj_b,
               const float* __restrict__ clsp_w, const float* __restrict__ clsp_b,
               const float* __restrict__ regp_w, const float* __restrict__ regp_b,
               float* __restrict__ out, float* __restrict__ best_s, int* __restrict__ cls_s)
{
    const int b = blockIdx.y;
    const int n = blockIdx.x * 160 + threadIdx.x;

    const float* cfb = cf + (long)b * HEAD * NPOS + n;
    const float* rfb = rf + (long)b * HEAD * NPOS + n;

    float accC[NCLS];
    float accR[4];
    float accO = 0.f;
#pragma unroll
    for (int c = 0; c < NCLS; c++) accC[c] = 0.f;
#pragma unroll
    for (int k = 0; k < 4; k++) accR[k] = 0.f;

#pragma unroll 4
    for (int ch = 0; ch < HEAD; ch++) {
        float cv = cfb[(long)ch * NPOS];
        float rv = rfb[(long)ch * NPOS];
        accO = fmaf(rv, __ldg(&obj_w[ch]), accO);
#pragma unroll
        for (int k = 0; k < 4; k++)
            accR[k] = fmaf(rv, __ldg(&regp_w[k * HEAD + ch]), accR[k]);
#pragma unroll
        for (int c = 0; c < NCLS; c++)
            accC[c] = fmaf(cv, __ldg(&clsp_w[c * HEAD + ch]), accC[c]);
    }

    accO += obj_b[0];
#pragma unroll
    for (int k = 0; k < 4; k++) accR[k] += regp_b[k];
#pragma unroll
    for (int c = 0; c < NCLS; c++) accC[c] += clsp_b[c];

    // softmax max / argmax (first-max tie-break, matching jnp.argmax)
    float m = accC[0];
    int am = 0;
#pragma unroll
    for (int c = 1; c < NCLS; c++)
        if (accC[c] > m) { m = accC[c]; am = c; }
    float s = 0.f;
#pragma unroll
    for (int c = 0; c < NCLS; c++) s += expf(accC[c] - m);
    float sig_o = 1.f / (1.f + expf(-accO));
    float best  = sig_o / s;   // sigmoid(obj) * softmax_max

    // box decode
    float gx = (float)(n % FMP);
    float gy = (float)(n / FMP);
    float cx = 1.f / (1.f + expf(-accR[0])) + gx;
    float cy = 1.f / (1.f + expf(-accR[1])) + gy;
    float ww = expf(accR[2]);
    float hh = expf(accR[3]);

    float bx1 = (cx - ww * 0.5f) * 32.f / 1280.f;
    float by1 = (cy - hh * 0.5f) * 32.f / 1280.f;
    float bx2 = (cx + ww * 0.5f) * 32.f / 1280.f;
    float by2 = (cy + hh * 0.5f) * 32.f / 1280.f;
    bx1 = fminf(fmaxf(bx1, 0.f), 1.f);
    by1 = fminf(fmaxf(by1, 0.f), 1.f);
    bx2 = fminf(fmaxf(bx2, 0.f), 1.f);
    by2 = fminf(fmaxf(by2, 0.f), 1.f);

    const int gi = b * NPOS + n;
    out[gi * 4 + 0] = bx1;
    out[gi * 4 + 1] = by1;
    out[gi * 4 + 2] = bx2;
    out[gi * 4 + 3] = by2;
    out[OFF_BEST + gi] = best;
    out[OFF_CLS  + gi] = (float)am;
    out[OFF_KEEP + gi] = 0.f;     // NMS sets kept ones to 1
    best_s[gi] = best;
    cls_s[gi]  = am;
}

// ---------------- per-(batch, class) greedy NMS ----------------
// grid: B*C = 160 blocks, 256 threads
__global__ void __launch_bounds__(256)
nms_k(const float* __restrict__ out_boxes,  // d_out (bbox region at offset 0)
      float* __restrict__ out_keep,         // d_out + OFF_KEEP
      const float* __restrict__ best_s, const int* __restrict__ cls_s)
{
    const int b = blockIdx.x / NCLS;
    const int c = blockIdx.x % NCLS;
    const int tid = threadIdx.x;

    __shared__ float sx1[NPOS], sy1[NPOS], sx2[NPOS], sy2[NPOS];
    __shared__ float ssc[NPOS];
    __shared__ int   sidx[NPOS];
    __shared__ unsigned short ord[NPOS];
    __shared__ unsigned char aliveR[NPOS];
    __shared__ int scnt;

    if (tid == 0) scnt = 0;
    __syncthreads();

    // gather candidates of this class
    for (int n = tid; n < NPOS; n += 256) {
        int gi = b * NPOS + n;
        if (cls_s[gi] == c && best_s[gi] >= CONF_T) {
            int p = atomicAdd(&scnt, 1);
            sidx[p] = n;
            ssc[p]  = best_s[gi];
            const float* bp = out_boxes + (long)gi * 4;
            sx1[p] = bp[0]; sy1[p] = bp[1]; sx2[p] = bp[2]; sy2[p] = bp[3];
        }
    }
    __syncthreads();
    const int cnt = scnt;

    // deterministic rank: score desc, original index asc (matches stable argsort of -score)
    for (int i = tid; i < cnt; i += 256) {
        float si = ssc[i];
        int   ii = sidx[i];
        int rnk = 0;
        for (int j = 0; j < cnt; j++) {
            float sj = ssc[j];
            if (sj > si || (sj == si && sidx[j] < ii)) rnk++;
        }
        ord[rnk] = (unsigned short)i;
        aliveR[rnk] = 1;
    }
    __syncthreads();

    // sequential greedy over rank order; parallel suppression within block
    for (int r = 0; r < cnt; r++) {
        __syncthreads();
        if (!aliveR[r]) continue;        // uniform (shared, post-sync)
        int li = ord[r];
        float bx1 = sx1[li], by1 = sy1[li], bx2 = sx2[li], by2 = sy2[li];
        float ai = (bx2 - bx1) * (by2 - by1);
        for (int rr = r + 1 + tid; rr < cnt; rr += 256) {
            if (!aliveR[rr]) continue;
            int lj = ord[rr];
            float jx1 = sx1[lj], jy1 = sy1[lj], jx2 = sx2[lj], jy2 = sy2[lj];
            float xx1 = fmaxf(bx1, jx1);
            float yy1 = fmaxf(by1, jy1);
            float xx2 = fminf(bx2, jx2);
            float yy2 = fminf(by2, jy2);
            float w2 = fmaxf(1e-28f, xx2 - xx1);
            float h2 = fmaxf(1e-28f, yy2 - yy1);
            float inter = w2 * h2;
            float aj = (jx2 - jx1) * (jy2 - jy1);
            float iou = inter / (ai + aj - inter + 1e-14f);
            if (iou > NMS_T) aliveR[rr] = 0;
        }
    }
    __syncthreads();

    for (int r = tid; r < cnt; r += 256)
        if (aliveR[r])
            out_keep[b * NPOS + sidx[ord[r]]] = 1.f;
}

// ---------------- launch ----------------
extern "C" void kernel_launch(void* const* d_in, const int* in_sizes, int n_in,
                              void* d_out, int out_size)
{
    const float* x      = (const float*)d_in[0];
    const float* cls_w  = (const float*)d_in[1];
    const float* cls_b  = (const float*)d_in[2];
    const float* reg_w  = (const float*)d_in[3];
    const float* reg_b  = (const float*)d_in[4];
    const float* obj_w  = (const float*)d_in[5];
    const float* obj_b  = (const float*)d_in[6];
    const float* clsp_w = (const float*)d_in[7];
    const float* clsp_b = (const float*)d_in[8];
    const float* regp_w = (const float*)d_in[9];
    const float* regp_b = (const float*)d_in[10];
    float* out = (float*)d_out;

    void *pA, *pB, *pC, *pBest, *pCls, *pWT;
    cudaGetSymbolAddress(&pA, g_bufA);
    cudaGetSymbolAddress(&pB, g_bufB);
    cudaGetSymbolAddress(&pC, g_bufC);
    cudaGetSymbolAddress(&pBest, g_best);
    cudaGetSymbolAddress(&pCls, g_clsi);
    cudaGetSymbolAddress(&pWT, g_wT);
    float* bufA = (float*)pA;
    float* bufB = (float*)pB;
    float* bufC = (float*)pC;
    float* bestp = (float*)pBest;
    int*   clsp  = (int*)pCls;
    float* wT    = (float*)pWT;

    // one-shot weight transform (deterministic, graph-capturable)
    {
        long total = 6 * WPER;
        int  grid  = (int)((total + 255) / 256);
        wtransform_k<<<grid, 256>>>(cls_w, reg_w, wT);
    }

    dim3 cgrid(FMP, 4, Bs);
    dim3 cblk(128);

    // cls branch: x -> bufA -> bufB   (cf = bufB)
    conv3x3_leaky_k<<<cgrid, cblk>>>(x,    wT + 0 * WPER, cls_b,        bufA);
    conv3x3_leaky_k<<<cgrid, cblk>>>(bufA, wT + 1 * WPER, cls_b + HEAD, bufB);
    // reg branch: x -> bufA -> bufC -> bufA -> bufC   (rf = bufC)
    conv3x3_leaky_k<<<cgrid, cblk>>>(x,    wT + 2 * WPER, reg_b,            bufA);
    conv3x3_leaky_k<<<cgrid, cblk>>>(bufA, wT + 3 * WPER, reg_b + HEAD,     bufC);
    conv3x3_leaky_k<<<cgrid, cblk>>>(bufC, wT + 4 * WPER, reg_b + 2 * HEAD, bufA);
    conv3x3_leaky_k<<<cgrid, cblk>>>(bufA, wT + 5 * WPER, reg_b + 3 * HEAD, bufC);

    heads_decode_k<<<dim3(10, Bs), 160>>>(bufB, bufC,
                                          obj_w, obj_b, clsp_w, clsp_b,
                                          regp_w, regp_b,
                                          out, bestp, clsp);

    nms_k<<<Bs * NCLS, 256>>>(out, out + OFF_KEEP, bestp, clsp);
}